// round 10
// baseline (speedup 1.0000x reference)
#include <cuda_runtime.h>

// x: (16, 256, 128, 128) fp32 -> 2x2 block sum * 0.5, then 2x2 NN upsample.
//
// R10: combine the two best-measured settings:
//   - access form from R6 (highest DRAM%): LDG.256/STG.256 + .cs streaming,
//     one v8 slot x one row pair per thread (2 loads + 2 stores).
//   - geometry from R9 (best bench time): 512-thread blocks.
//
// Row = 128 floats = 16 v8 slots; 16*256*64 row pairs x 16 slots =
// 4,194,304 threads = 8192 CTAs @ 512.

__global__ void __launch_bounds__(512) wfdm_kernel(
    const float* __restrict__ in, float* __restrict__ out)
{
    int tid = blockIdx.x * blockDim.x + threadIdx.x;

    int col   = tid & 15;      // v8 slot within row (0..15), lane-contiguous
    int group = tid >> 4;      // row pair index

    long base = (long)group * 256 + (long)col * 8;  // 2 rows * 128 floats

    const float* p0 = in + base;        // top row
    const float* p1 = p0 + 128;         // bottom row

    float a0, a1, a2, a3, a4, a5, a6, a7;   // top row
    float b0, b1, b2, b3, b4, b5, b6, b7;   // bottom row

    asm volatile(
        "ld.global.cs.v8.f32 {%0,%1,%2,%3,%4,%5,%6,%7}, [%8];"
        : "=f"(a0), "=f"(a1), "=f"(a2), "=f"(a3),
          "=f"(a4), "=f"(a5), "=f"(a6), "=f"(a7)
        : "l"(p0));
    asm volatile(
        "ld.global.cs.v8.f32 {%0,%1,%2,%3,%4,%5,%6,%7}, [%8];"
        : "=f"(b0), "=f"(b1), "=f"(b2), "=f"(b3),
          "=f"(b4), "=f"(b5), "=f"(b6), "=f"(b7)
        : "l"(p1));

    float s0 = (a0 + a1 + b0 + b1) * 0.5f;
    float s1 = (a2 + a3 + b2 + b3) * 0.5f;
    float s2 = (a4 + a5 + b4 + b5) * 0.5f;
    float s3 = (a6 + a7 + b6 + b7) * 0.5f;

    float* q0 = out + base;
    float* q1 = q0 + 128;

    asm volatile(
        "st.global.cs.v8.f32 [%0], {%1,%2,%3,%4,%5,%6,%7,%8};"
        :: "l"(q0),
           "f"(s0), "f"(s0), "f"(s1), "f"(s1),
           "f"(s2), "f"(s2), "f"(s3), "f"(s3)
        : "memory");
    asm volatile(
        "st.global.cs.v8.f32 [%0], {%1,%2,%3,%4,%5,%6,%7,%8};"
        :: "l"(q1),
           "f"(s0), "f"(s0), "f"(s1), "f"(s1),
           "f"(s2), "f"(s2), "f"(s3), "f"(s3)
        : "memory");
}

extern "C" void kernel_launch(void* const* d_in, const int* in_sizes, int n_in,
                              void* d_out, int out_size)
{
    const float* in = (const float*)d_in[0];
    float* out = (float*)d_out;

    // total threads = elements / 16 (each thread covers 16 floats)
    int total = out_size / 16;   // 16*256*128*128 / 16 = 4,194,304
    int threads = 512;
    int blocks = total / threads;  // exact: 8192
    wfdm_kernel<<<blocks, threads>>>(in, out);
}